// round 14
// baseline (speedup 1.0000x reference)
#include <cuda_runtime.h>
#include <cuda_fp16.h>

typedef unsigned int u32;

// Problem constants
#define NB   8
#define NT   4096
#define ND   512
#define NDI  1024
#define NM   (NB * NT)   // 32768 rows (B*T)

// ---------------------------------------------------------------------------
// Scratch (static __device__ arrays; no allocations allowed)
// ---------------------------------------------------------------------------
__device__ __half g_xh [NM * ND];        // x fp16 (GEMM1 A)
__device__ __half g_wi [2 * NDI * ND];   // in_proj_w fp16
__device__ __half g_wpf[NDI * NDI];      // proj_fwd_w fp16
__device__ __half g_wpb[NDI * NDI];      // proj_bwd_w fp16
__device__ __half g_wo [ND * NDI];       // out_proj_w fp16
__device__ float  g_cwf[7 * NDI];        // conv fwd w, [tap][chan] fp32
__device__ float  g_cwb[7 * NDI];        // conv bwd w, [tap][chan] fp32
__device__ __half g_Xp[NM * NDI];        // x_proj fp16
__device__ __half g_Z [NM * NDI];        // z fp16
__device__ __half g_Af[NM * NDI];        // conv fwd out fp16
__device__ __half g_Ab[NM * NDI];        // conv bwd out fp16
__device__ __half g_Sf[NM * NDI];        // silu(proj_fwd + bias) fp16
__device__ __half g_Y [NM * NDI];        // gated mixer output fp16
__device__ float  g_H [NM * ND];         // residual + out_proj (fp32)

__device__ __forceinline__ float silu_f(float x) {
    return x / (1.0f + __expf(-x));
}

__device__ __forceinline__ u32 smem_u32(const void* p) {
    u32 a;
    asm("{ .reg .u64 t; cvta.to.shared.u64 t, %1; cvt.u32.u64 %0, t; }"
        : "=r"(a) : "l"(p));
    return a;
}

// ---------------------------------------------------------------------------
// PTX primitives: cp.async, ldmatrix, mma (all compute_103-base legal)
// ---------------------------------------------------------------------------
__device__ __forceinline__ void cpa16(u32 s, const void* g) {
    asm volatile("cp.async.cg.shared.global [%0], [%1], 16;" :: "r"(s), "l"(g));
}
#define CP_COMMIT()  asm volatile("cp.async.commit_group;" ::: "memory")
#define CP_WAIT(N)   asm volatile("cp.async.wait_group %0;" :: "n"(N) : "memory")

#define LDSM4(r0, r1, r2, r3, addr) \
    asm volatile("ldmatrix.sync.aligned.m8n8.x4.shared.b16 {%0,%1,%2,%3}, [%4];" \
        : "=r"(r0), "=r"(r1), "=r"(r2), "=r"(r3) : "r"(addr))

// f16 x f16 -> f16 accumulate
#define MMA16816H(c, a, b) \
    asm volatile("mma.sync.aligned.m16n8k16.row.col.f16.f16.f16.f16 " \
        "{%0,%1}, {%2,%3,%4,%5}, {%6,%7}, {%0,%1};" \
        : "+r"((c)[0]), "+r"((c)[1]) \
        : "r"((a)[0]), "r"((a)[1]), "r"((a)[2]), "r"((a)[3]), \
          "r"((b)[0]), "r"((b)[1]))

// ---------------------------------------------------------------------------
// Warp-MMA GEMM: C[m,n] = sum_k A[m,k]*W[n,k], fp16 in, fp16 accum.
// BM=128, BN=256, BK=64, 256 threads = 8 warps (2M x 4N), 64x64 warp tiles.
// SW128-swizzled smem, 2-stage cp.async pipeline (48KB/stage), 1 barrier/slab.
// mode 0: split: tile n0 < NDI -> o0 (Xp), else o1 (Z)    [fp16]
// mode 1: o0[m,n] = h( silu(acc + bias[n]) )              [fp16]
// mode 2: of[m,n] = acc + resid[m,n]                      [fp32]
// mode 3: sb = silu(acc + bias[n]);  (combine fused)
//         y = (fm*Sf + bm*sb + Xp*diag) * silu(Z) * gs -> o0 (Y) [fp16]
// ---------------------------------------------------------------------------
#define ST_BYTES  49152u                  // 48KB per stage (A 16KB + B 32KB)
#define GEMM_SMEM (1024 + 2 * 49152)

__global__ __launch_bounds__(256, 2)
void gemm_mma(const __half* __restrict__ A, const __half* __restrict__ W,
              int K, int mode,
              __half* __restrict__ o0, __half* __restrict__ o1,
              const float* __restrict__ bias, const float* __restrict__ resid,
              float* __restrict__ of, int Nout,
              const __half* __restrict__ eSf, const __half* __restrict__ eXp,
              const __half* __restrict__ eZ,
              const float* __restrict__ diag, const float* __restrict__ gsp)
{
    extern __shared__ char dsm[];
    const u32 dyn  = smem_u32(dsm);
    const u32 base = (dyn + 1023u) & ~1023u;

    const int tid  = threadIdx.x;
    const int wid  = tid >> 5;
    const int lane = tid & 31;
    const int m0   = blockIdx.y << 7;
    const int n0   = blockIdx.x << 8;     // BN = 256
    const int warp_m = wid >> 2;          // 0..1
    const int warp_n = wid & 3;           // 0..3

    // ---- cp.async: base chunk (row = tid>>3, 16B col = tid&7); chunk i adds
    //      32 rows (swizzle XOR invariant under row+32).
    const int lrow = tid >> 3;            // 0..31
    const int lch  = tid & 7;
    const u32 sw0  = (u32)(lrow * 128 + ((lch * 16) ^ ((lrow & 7) << 4)));
    const __half* gA0 = A + (size_t)(m0 + lrow) * K + lch * 8;
    const __half* gB0 = W + (size_t)(n0 + lrow) * K + lch * 8;
    const size_t rstep = (size_t)32 * K;

    // ---- ldmatrix per-lane address components ----
    const int blk = lane >> 3;            // 0..3
    const int lr  = lane & 7;
    int aRow[4], aXr[4];
#pragma unroll
    for (int mi = 0; mi < 4; ++mi) {
        const int r = warp_m * 64 + mi * 16 + (blk & 1) * 8 + lr;
        aRow[mi] = r * 128;
        aXr[mi]  = (r & 7) << 4;
    }
    const int koA = (blk >> 1) * 16;
    int bRow[4], bXr[4];
#pragma unroll
    for (int np = 0; np < 4; ++np) {
        const int r = warp_n * 64 + np * 16 + (blk >> 1) * 8 + lr;
        bRow[np] = r * 128;
        bXr[np]  = (r & 7) << 4;
    }
    const int koB = (blk & 1) * 16;

    // f16x2 accumulators: [mi][ni][2 regs of 2 halves] = 64 regs
    u32 acc[4][8][2];
#pragma unroll
    for (int mi = 0; mi < 4; ++mi)
#pragma unroll
        for (int ni = 0; ni < 8; ++ni) { acc[mi][ni][0] = 0u; acc[mi][ni][1] = 0u; }

    const int S = K >> 6;

    // ---- prologue: slab 0 into stage 0 ----
#pragma unroll
    for (int i = 0; i < 4; ++i)
        cpa16(base + sw0 + i * 4096u, gA0 + (size_t)i * rstep);
#pragma unroll
    for (int i = 0; i < 8; ++i)
        cpa16(base + 16384u + sw0 + i * 4096u, gB0 + (size_t)i * rstep);
    CP_COMMIT();

    for (int s = 0; s < S; ++s) {
        CP_WAIT(0);
        __syncthreads();

        if (s + 1 < S) {
            const u32 st = base + (u32)((s + 1) & 1) * ST_BYTES;
            const int k0 = (s + 1) << 6;
#pragma unroll
            for (int i = 0; i < 4; ++i)
                cpa16(st + sw0 + i * 4096u, gA0 + (size_t)i * rstep + k0);
#pragma unroll
            for (int i = 0; i < 8; ++i)
                cpa16(st + 16384u + sw0 + i * 4096u, gB0 + (size_t)i * rstep + k0);
            CP_COMMIT();
        }

        const u32 sa = base + (u32)(s & 1) * ST_BYTES;
        const u32 sb = sa + 16384u;
#pragma unroll
        for (int kk = 0; kk < 4; ++kk) {
            u32 a[4][4];
#pragma unroll
            for (int mi = 0; mi < 4; ++mi) {
                const u32 ad = sa + aRow[mi] + ((kk * 32 + koA) ^ aXr[mi]);
                LDSM4(a[mi][0], a[mi][1], a[mi][2], a[mi][3], ad);
            }
            u32 b[8][2];
#pragma unroll
            for (int np = 0; np < 4; ++np) {
                const u32 bd = sb + bRow[np] + ((kk * 32 + koB) ^ bXr[np]);
                LDSM4(b[2*np][0], b[2*np][1], b[2*np+1][0], b[2*np+1][1], bd);
            }
#pragma unroll
            for (int mi = 0; mi < 4; ++mi)
#pragma unroll
                for (int ni = 0; ni < 8; ++ni)
                    MMA16816H(acc[mi][ni], a[mi], b[ni]);
        }
    }

    // ---- epilogue ----
    const int mrow0 = m0 + warp_m * 64 + (lane >> 2);
    const int ncol0 = n0 + warp_n * 64 + (lane & 3) * 2;

    if (mode == 2) {
#pragma unroll
        for (int mi = 0; mi < 4; ++mi) {
#pragma unroll
            for (int ni = 0; ni < 8; ++ni) {
                const int m = mrow0 + mi * 16;
                const int n = ncol0 + ni * 8;
                const float2 c01 = __half22float2(*(__half2*)&acc[mi][ni][0]);
                const float2 c23 = __half22float2(*(__half2*)&acc[mi][ni][1]);
                float2 r0 = *(const float2*)(resid + (size_t)m * Nout + n);
                float2 r1 = *(const float2*)(resid + (size_t)(m + 8) * Nout + n);
                float2 v0 = { c01.x + r0.x, c01.y + r0.y };
                float2 v1 = { c23.x + r1.x, c23.y + r1.y };
                *(float2*)(of + (size_t)m * Nout + n)       = v0;
                *(float2*)(of + (size_t)(m + 8) * Nout + n) = v1;
            }
        }
    } else if (mode == 3) {
        const float gs = gsp[0];
#pragma unroll
        for (int mi = 0; mi < 4; ++mi) {
            const int m  = mrow0 + mi * 16;
            const int t0 = m & (NT - 1);
            const int t1 = (m + 8) & (NT - 1);
            const float fm0 = (t0 > 0) ? 1.0f : 0.0f;
            const float bm0 = (t0 < NT - 1) ? 1.0f : 0.0f;
            const float fm1 = (t1 > 0) ? 1.0f : 0.0f;
            const float bm1 = (t1 < NT - 1) ? 1.0f : 0.0f;
#pragma unroll
            for (int ni = 0; ni < 8; ++ni) {
                const int n = ncol0 + ni * 8;
                const size_t o0i = (size_t)m * NDI + n;
                const size_t o1i = (size_t)(m + 8) * NDI + n;
                const float2 dg = *(const float2*)(diag + n);
                const float b0 = bias[n], b1 = bias[n + 1];

                const float2 c01 = __half22float2(*(__half2*)&acc[mi][ni][0]);
                const float2 c23 = __half22float2(*(__half2*)&acc[mi][ni][1]);

                float2 sf0 = __half22float2(*(const __half2*)(eSf + o0i));
                float2 sf1 = __half22float2(*(const __half2*)(eSf + o1i));
                float2 xp0 = __half22float2(*(const __half2*)(eXp + o0i));
                float2 xp1 = __half22float2(*(const __half2*)(eXp + o1i));
                float2 z0  = __half22float2(*(const __half2*)(eZ  + o0i));
                float2 z1  = __half22float2(*(const __half2*)(eZ  + o1i));

                const float sb00 = silu_f(c01.x + b0);
                const float sb01 = silu_f(c01.y + b1);
                const float sb10 = silu_f(c23.x + b0);
                const float sb11 = silu_f(c23.y + b1);

                float y00 = (fm0 * sf0.x + bm0 * sb00 + xp0.x * dg.x) * silu_f(z0.x) * gs;
                float y01 = (fm0 * sf0.y + bm0 * sb01 + xp0.y * dg.y) * silu_f(z0.y) * gs;
                float y10 = (fm1 * sf1.x + bm1 * sb10 + xp1.x * dg.x) * silu_f(z1.x) * gs;
                float y11 = (fm1 * sf1.y + bm1 * sb11 + xp1.y * dg.y) * silu_f(z1.y) * gs;

                *(__half2*)(o0 + o0i) = __floats2half2_rn(y00, y01);
                *(__half2*)(o0 + o1i) = __floats2half2_rn(y10, y11);
            }
        }
    } else {
        __half* dst = o0;
        int nsub = 0;
        if (mode == 0 && n0 >= NDI) { dst = o1; nsub = NDI; }
#pragma unroll
        for (int mi = 0; mi < 4; ++mi) {
#pragma unroll
            for (int ni = 0; ni < 8; ++ni) {
                const int m = mrow0 + mi * 16;
                const int n = ncol0 + ni * 8;
                float2 c01 = __half22float2(*(__half2*)&acc[mi][ni][0]);
                float2 c23 = __half22float2(*(__half2*)&acc[mi][ni][1]);
                if (mode == 1) {
                    const float b0 = bias[n], b1 = bias[n + 1];
                    c01.x = silu_f(c01.x + b0); c01.y = silu_f(c01.y + b1);
                    c23.x = silu_f(c23.x + b0); c23.y = silu_f(c23.y + b1);
                }
                const int nl = n - nsub;
                *(__half2*)(dst + (size_t)m * NDI + nl)       = __floats2half2_rn(c01.x, c01.y);
                *(__half2*)(dst + (size_t)(m + 8) * NDI + nl) = __floats2half2_rn(c23.x, c23.y);
            }
        }
    }
}

// ---------------------------------------------------------------------------
// Fused prep: converts x, wi, wpf, wpb, wo fp32->fp16 in ONE kernel, plus
// conv weight transpose at the tail. Unit = 4 floats.
// ---------------------------------------------------------------------------
#define U_X   (NM * ND / 4)
#define U_WI  (U_X  + 2 * NDI * ND / 4)
#define U_WPF (U_WI + NDI * NDI / 4)
#define U_WPB (U_WPF + NDI * NDI / 4)
#define U_WO  (U_WPB + ND * NDI / 4)
#define U_CW  (U_WO + 7 * NDI / 4)

__global__ __launch_bounds__(256)
void prep_kernel(const float* __restrict__ x,   const float* __restrict__ wi,
                 const float* __restrict__ wpf, const float* __restrict__ wpb,
                 const float* __restrict__ wo,
                 const float* __restrict__ cwf, const float* __restrict__ cwb)
{
    const int i = blockIdx.x * blockDim.x + threadIdx.x;
    if (i >= U_CW) return;

    if (i < U_WO) {
        const float* src;
        __half* dst;
        int off;
        if (i < U_X)        { src = x;   dst = g_xh;  off = i; }
        else if (i < U_WI)  { src = wi;  dst = g_wi;  off = i - U_X; }
        else if (i < U_WPF) { src = wpf; dst = g_wpf; off = i - U_WI; }
        else if (i < U_WPB) { src = wpb; dst = g_wpb; off = i - U_WPF; }
        else                { src = wo;  dst = g_wo;  off = i - U_WPB; }
        const float4 v = ((const float4*)src)[off];
        __half2 h0 = __floats2half2_rn(v.x, v.y);
        __half2 h1 = __floats2half2_rn(v.z, v.w);
        uint2 o;
        o.x = *(u32*)&h0; o.y = *(u32*)&h1;
        ((uint2*)dst)[off] = o;
    } else {
        const int e0 = (i - U_WO) * 4;
#pragma unroll
        for (int q = 0; q < 4; ++q) {
            const int e = e0 + q;
            const int j = e / NDI, c = e - j * NDI;
            g_cwf[e] = cwf[c * 7 + j];
            g_cwb[e] = cwb[c * 7 + j];
        }
    }
}

// ---------------------------------------------------------------------------
// Depthwise causal (fwd) + anti-causal (bwd) conv, smem-tiled, fp16.
// Tile: 128 t-rows x 64 channels; strip of 142 rows loaded once.
// ---------------------------------------------------------------------------
#define CT_M 128
#define CT_C 64

__device__ __forceinline__ void unpack8h(uint4 v, float* f) {
    float2 p;
    p = __half22float2(*(__half2*)&v.x); f[0] = p.x; f[1] = p.y;
    p = __half22float2(*(__half2*)&v.y); f[2] = p.x; f[3] = p.y;
    p = __half22float2(*(__half2*)&v.z); f[4] = p.x; f[5] = p.y;
    p = __half22float2(*(__half2*)&v.w); f[6] = p.x; f[7] = p.y;
}

__device__ __forceinline__ uint4 pack8h(const float* f) {
    u32 pk[4];
#pragma unroll
    for (int j = 0; j < 4; ++j) {
        __half2 h = __floats2half2_rn(f[2*j], f[2*j+1]);
        pk[j] = *(u32*)&h;
    }
    return *(uint4*)pk;
}

__global__ __launch_bounds__(256)
void conv_kernel(const float* __restrict__ bfc, const float* __restrict__ bbc)
{
    __shared__ __half sx[142][CT_C];
    __shared__ float swf[7][CT_C], swb[7][CT_C];
    __shared__ float sbf[CT_C], sbb[CT_C];

    const int c0  = blockIdx.x * CT_C;
    const int m0  = blockIdx.y * CT_M;
    const int lo  = m0 & ~(NT - 1);
    const int hi  = lo + NT;
    const int tid = threadIdx.x;

    if (tid < 7 * CT_C / 8) {
        const int j = tid >> 3, cc = (tid & 7) * 8;
        *(float4*)&swf[j][cc]     = *(const float4*)(g_cwf + j * NDI + c0 + cc);
        *(float4*)&swf[j][cc + 4] = *(const float4*)(g_cwf + j * NDI + c0 + cc + 4);
        *(float4*)&swb[j][cc]     = *(const float4*)(g_cwb + j * NDI + c0 + cc);
        *(float4*)&swb[j][cc + 4] = *(const float4*)(g_cwb + j * NDI + c0 + cc + 4);
    }
    if (tid >= 64 && tid < 64 + CT_C / 4) {
        const int q = (tid - 64) * 4;
        *(float4*)&sbf[q] = *(const float4*)(bfc + c0 + q);
        *(float4*)&sbb[q] = *(const float4*)(bbc + c0 + q);
    }

    for (int u = tid; u < 142 * 8; u += 256) {
        const int r = u >> 3, cc = (u & 7) * 8;
        const int m = m0 - 7 + r;
        uint4 v = make_uint4(0, 0, 0, 0);
        if (m >= lo && m < hi)
            v = *(const uint4*)(g_Xp + (size_t)m * NDI + c0 + cc);
        *(uint4*)&sx[r][cc] = v;
    }
    __syncthreads();

    for (int u = tid; u < CT_M * 8; u += 256) {
        const int r  = u >> 3, cc = (u & 7) * 8;
        const int m  = m0 + r;
        float accf[8], accb[8];
#pragma unroll
        for (int q = 0; q < 8; ++q) { accf[q] = sbf[cc + q]; accb[q] = sbb[cc + q]; }
#pragma unroll
        for (int k = 0; k < 7; ++k) {
            float xf[8], xb[8];
            unpack8h(*(const uint4*)&sx[r + k][cc], xf);
            unpack8h(*(const uint4*)&sx[r + 14 - k][cc], xb);
#pragma unroll
            for (int q = 0; q < 8; ++q) {
                accf[q] = fmaf(swf[k][cc + q], xf[q], accf[q]);
                accb[q] = fmaf(swb[k][cc + q], xb[q], accb[q]);
            }
        }
        const size_t o = (size_t)m * NDI + c0 + cc;
        *(uint4*)(g_Af + o) = pack8h(accf);
        *(uint4*)(g_Ab + o) = pack8h(accb);
    }
}

// ---------------------------------------------------------------------------
// LayerNorm over last dim (512), one block (128 threads) per row.
// ---------------------------------------------------------------------------
__global__ void ln_kernel(const float* __restrict__ lng, const float* __restrict__ lnb,
                          float* __restrict__ out)
{
    const int row = blockIdx.x;
    const int tid = threadIdx.x;

    const float4 v = ((const float4*)(g_H + (size_t)row * ND))[tid];
    float s  = v.x + v.y + v.z + v.w;
    float ss = v.x*v.x + v.y*v.y + v.z*v.z + v.w*v.w;

#pragma unroll
    for (int o = 16; o > 0; o >>= 1) {
        s  += __shfl_xor_sync(0xffffffffu, s,  o);
        ss += __shfl_xor_sync(0xffffffffu, ss, o);
    }
    __shared__ float shs[4], shss[4];
    if ((tid & 31) == 0) { shs[tid >> 5] = s; shss[tid >> 5] = ss; }
    __syncthreads();
    s  = shs[0]  + shs[1]  + shs[2]  + shs[3];
    ss = shss[0] + shss[1] + shss[2] + shss[3];

    const float mu  = s * (1.0f / ND);
    const float var = ss * (1.0f / ND) - mu * mu;
    const float inv = rsqrtf(var + 1e-5f);

    const float4 g4 = ((const float4*)lng)[tid];
    const float4 b4 = ((const float4*)lnb)[tid];
    float4 o4;
    o4.x = (v.x - mu) * inv * g4.x + b4.x;
    o4.y = (v.y - mu) * inv * g4.y + b4.y;
    o4.z = (v.z - mu) * inv * g4.z + b4.z;
    o4.w = (v.w - mu) * inv * g4.w + b4.w;
    ((float4*)(out + (size_t)row * ND))[tid] = o4;
}

// ---------------------------------------------------------------------------
// Launch
// ---------------------------------------------------------------------------
extern "C" void kernel_launch(void* const* d_in, const int* in_sizes, int n_in,
                              void* d_out, int out_size)
{
    const float* x    = (const float*)d_in[0];
    const float* winp = (const float*)d_in[1];
    const float* wcf  = (const float*)d_in[2];
    const float* bcf  = (const float*)d_in[3];
    const float* wpf  = (const float*)d_in[4];
    const float* bpf  = (const float*)d_in[5];
    const float* wcb  = (const float*)d_in[6];
    const float* bcb  = (const float*)d_in[7];
    const float* wpb  = (const float*)d_in[8];
    const float* bpb  = (const float*)d_in[9];
    const float* diag = (const float*)d_in[10];
    const float* gsc  = (const float*)d_in[11];
    const float* wout = (const float*)d_in[12];
    const float* lng  = (const float*)d_in[13];
    const float* lnb  = (const float*)d_in[14];
    float* out = (float*)d_out;

    __half *pxh, *pwi, *pwpf, *pwpb, *pwo;
    __half *pXp, *pZ, *pAf, *pAb, *pSf, *pY;
    float *pH;
    cudaGetSymbolAddress((void**)&pxh,  g_xh);
    cudaGetSymbolAddress((void**)&pwi,  g_wi);
    cudaGetSymbolAddress((void**)&pwpf, g_wpf);
    cudaGetSymbolAddress((void**)&pwpb, g_wpb);
    cudaGetSymbolAddress((void**)&pwo,  g_wo);
    cudaGetSymbolAddress((void**)&pXp,  g_Xp);
    cudaGetSymbolAddress((void**)&pZ,   g_Z);
    cudaGetSymbolAddress((void**)&pAf,  g_Af);
    cudaGetSymbolAddress((void**)&pAb,  g_Ab);
    cudaGetSymbolAddress((void**)&pSf,  g_Sf);
    cudaGetSymbolAddress((void**)&pY,   g_Y);
    cudaGetSymbolAddress((void**)&pH,   g_H);

    cudaFuncSetAttribute(gemm_mma, cudaFuncAttributeMaxDynamicSharedMemorySize, GEMM_SMEM);

    // 0) all fp32->fp16 conversions + conv weight transpose in ONE launch
    prep_kernel<<<(U_CW + 255) / 256, 256>>>(x, winp, wpf, wpb, wout, wcf, wcb);

    // 1) in_proj: split into Xp, Z (fp16);  N = 2048 -> 8 col blocks of 256
    gemm_mma<<<dim3(2 * NDI / 256, NM / 128), 256, GEMM_SMEM>>>(
        pxh, pwi, ND, 0, pXp, pZ, nullptr, nullptr, nullptr, 2 * NDI,
        nullptr, nullptr, nullptr, nullptr, nullptr);

    // 2) depthwise convs -> Af, Ab (fp16)
    conv_kernel<<<dim3(NDI / CT_C, NM / CT_M), 256>>>(bcf, bcb);

    // 3) fwd proj with fused bias + silu -> Sf (fp16);  N = 1024 -> 4 blocks
    gemm_mma<<<dim3(NDI / 256, NM / 128), 256, GEMM_SMEM>>>(
        pAf, pwpf, NDI, 1, pSf, nullptr, bpf, nullptr, nullptr, NDI,
        nullptr, nullptr, nullptr, nullptr, nullptr);

    // 4) bwd proj with fused bias + silu + combine + gate -> Y (fp16)
    gemm_mma<<<dim3(NDI / 256, NM / 128), 256, GEMM_SMEM>>>(
        pAb, pwpb, NDI, 3, pY, nullptr, bpb, nullptr, nullptr, NDI,
        pSf, pXp, pZ, diag, gsc);

    // 5) out_proj + residual -> H (fp32);  N = 512 -> 2 blocks
    gemm_mma<<<dim3(ND / 256, NM / 128), 256, GEMM_SMEM>>>(
        pY, pwo, NDI, 2, nullptr, nullptr, nullptr, x, pH, ND,
        nullptr, nullptr, nullptr, nullptr, nullptr);

    // 6) LayerNorm -> out
    ln_kernel<<<NM, 128>>>(lng, lnb, out);
}